// round 4
// baseline (speedup 1.0000x reference)
#include <cuda_runtime.h>
#include <cuda_bf16.h>
#include <cstdint>

#define NMAX 50000
#define EMAX 600000
#define TEMAX (EMAX + NMAX)

// ---------------- scratch (device globals; no allocation allowed) -------------
__device__ float g_xh1[(size_t)NMAX * 256];
__device__ float g_z1 [(size_t)NMAX * 256];
__device__ float g_xh2[(size_t)NMAX * 64];
__device__ float g_z2 [(size_t)NMAX * 64];
__device__ float g_as1[NMAX * 2];
__device__ float g_ad1[NMAX * 2];
__device__ float g_as2[NMAX];
__device__ float g_ad2[NMAX];
__device__ int   g_counts[NMAX];
__device__ int   g_cursor[NMAX];
__device__ int   g_rowptr[NMAX + 1];
__device__ int   g_esrc[TEMAX];
__device__ int   g_src[EMAX];
__device__ int   g_dst[EMAX];
__device__ int   g_is64;

// ---------------- edge dtype detect + convert --------------------------------
// int64 layout: odd 32-bit words are high words == 0 (node ids < 2^31).
// int32 layout: odd words are real node ids (nonzero with certainty over ~512 samples).
__global__ void k_detect(const unsigned* __restrict__ w, int nwords) {
    __shared__ int flag;
    if (threadIdx.x == 0) flag = 0;
    __syncthreads();
    for (int i = 1 + 2 * threadIdx.x; i < nwords; i += 2 * blockDim.x)
        if (w[i] != 0u) flag = 1;
    __syncthreads();
    if (threadIdx.x == 0) g_is64 = (flag == 0);
}

__global__ void k_cvt(int E, const void* __restrict__ p) {
    int e = blockIdx.x * blockDim.x + threadIdx.x;
    if (e >= E) return;
    if (g_is64) {
        const long long* q = (const long long*)p;
        g_src[e] = (int)q[e];
        g_dst[e] = (int)q[E + e];
    } else {
        const int* q = (const int*)p;
        g_src[e] = q[e];
        g_dst[e] = q[E + e];
    }
}

// ---------------- CSR build --------------------------------------------------
__global__ void k_zero_counts(int N) {
    int i = blockIdx.x * blockDim.x + threadIdx.x;
    if (i < N) g_counts[i] = 0;
}

__global__ void k_hist(int E, int N) {
    int i = blockIdx.x * blockDim.x + threadIdx.x;
    int TE = E + N;
    if (i >= TE) return;
    int dst = (i < E) ? g_dst[i] : (i - E);
    atomicAdd(&g_counts[dst], 1);
}

// single-block exclusive scan (Hillis-Steele per 1024 chunk + running carry)
__global__ void k_scan(int N) {
    __shared__ int sh[1024];
    __shared__ int carry;
    int t = threadIdx.x;
    if (t == 0) carry = 0;
    __syncthreads();
    for (int base = 0; base < N; base += 1024) {
        int v = (base + t < N) ? g_counts[base + t] : 0;
        sh[t] = v;
        __syncthreads();
        for (int off = 1; off < 1024; off <<= 1) {
            int x = (t >= off) ? sh[t - off] : 0;
            __syncthreads();
            sh[t] += x;
            __syncthreads();
        }
        int incl = sh[t];
        if (base + t < N) {
            int excl = carry + incl - v;
            g_rowptr[base + t] = excl;
            g_cursor[base + t] = excl;
        }
        __syncthreads();
        if (t == 1023) carry += sh[1023];
        __syncthreads();
    }
    if (t == 0) g_rowptr[N] = carry;
}

__global__ void k_scatter(int E, int N) {
    int i = blockIdx.x * blockDim.x + threadIdx.x;
    int TE = E + N;
    if (i >= TE) return;
    int src, dst;
    if (i < E) { src = g_src[i]; dst = g_dst[i]; }
    else       { src = dst = i - E; }
    int pos = atomicAdd(&g_cursor[dst], 1);
    g_esrc[pos] = src;
}

// ---------------- SGEMM (C = A[MxK] * B[KxN], all row-major) -----------------
// MODE 0: C = g_xh1, A = param; MODE 1: C = g_xh2, A = g_z1
template<int BM, int BN, int BK, int TM, int TN, int MODE>
__global__ void k_sgemm(int M, int N, int K,
                        const float* __restrict__ Ain,
                        const float* __restrict__ B) {
    const float* __restrict__ A = (MODE == 0) ? Ain : g_z1;
    float* __restrict__ C = (MODE == 0) ? g_xh1 : g_xh2;
    __shared__ float As[BK][BM];
    __shared__ float Bs[BK][BN];
    const int tid  = threadIdx.x;                 // 256 threads
    const int tcol = tid % (BN / TN);
    const int trow = tid / (BN / TN);
    const int rowBase = blockIdx.y * BM;
    const int colBase = blockIdx.x * BN;

    float acc[TM][TN];
#pragma unroll
    for (int i = 0; i < TM; i++)
#pragma unroll
        for (int j = 0; j < TN; j++) acc[i][j] = 0.f;

    for (int k0 = 0; k0 < K; k0 += BK) {
#pragma unroll
        for (int i = tid; i < BM * BK; i += 256) {
            int m = i / BK, kk = i % BK;
            int gm = rowBase + m;
            As[kk][m] = (gm < M) ? A[(size_t)gm * K + k0 + kk] : 0.f;
        }
#pragma unroll
        for (int i = tid; i < BK * BN; i += 256) {
            int kk = i / BN, nn = i % BN;
            Bs[kk][nn] = B[(size_t)(k0 + kk) * N + colBase + nn];
        }
        __syncthreads();
#pragma unroll
        for (int kk = 0; kk < BK; kk++) {
            float ra[TM], rb[TN];
#pragma unroll
            for (int i = 0; i < TM; i++) ra[i] = As[kk][trow * TM + i];
#pragma unroll
            for (int j = 0; j < TN; j++) rb[j] = Bs[kk][tcol * TN + j];
#pragma unroll
            for (int i = 0; i < TM; i++)
#pragma unroll
                for (int j = 0; j < TN; j++) acc[i][j] += ra[i] * rb[j];
        }
        __syncthreads();
    }
#pragma unroll
    for (int i = 0; i < TM; i++) {
        int gm = rowBase + trow * TM + i;
        if (gm >= M) continue;
#pragma unroll
        for (int j = 0; j < TN; j++) {
            int gn = colBase + tcol * TN + j;
            C[(size_t)gm * N + gn] = acc[i][j];
        }
    }
}

// ---------------- attention logits: a_src/a_dst per (node, head) -------------
// blockDim = H*C (<=256); one node per block. MODE 0: layer1, MODE 1: layer2.
template<int H, int C, int MODE>
__global__ void k_att(const float* __restrict__ att_s,
                      const float* __restrict__ att_d) {
    const float* __restrict__ xh = (MODE == 0) ? g_xh1 : g_xh2;
    float* __restrict__ a_s = (MODE == 0) ? g_as1 : g_as2;
    float* __restrict__ a_d = (MODE == 0) ? g_ad1 : g_ad2;
    __shared__ float ss[256], sd[256];
    int n = blockIdx.x, t = threadIdx.x;
    const int HC = H * C;
    float v = xh[(size_t)n * HC + t];
    ss[t] = v * att_s[t];
    sd[t] = v * att_d[t];
    __syncthreads();
    for (int off = C / 2; off > 0; off >>= 1) {
        if ((t & (C - 1)) < off) { ss[t] += ss[t + off]; sd[t] += sd[t + off]; }
        __syncthreads();
    }
    if ((t & (C - 1)) == 0) {
        int h = t / C;
        a_s[n * H + h] = ss[t];
        a_d[n * H + h] = sd[t];
    }
}

// ---------------- layer-1 aggregation (H=2, C=128): block=256 per node -------
#define CHUNK1 64
__global__ void k_agg1(const float* __restrict__ bias) {
    const float* __restrict__ xh = g_xh1;
    int n = blockIdx.x, t = threadIdx.x;      // t in [0,256)
    int h = t >> 7;
    __shared__ int   ssrc[CHUNK1];
    __shared__ float sw[CHUNK1 * 2];
    int beg = g_rowptr[n], end = g_rowptr[n + 1];
    float acc = 0.f, den = 0.f;
    for (int cs = beg; cs < end; cs += CHUNK1) {
        int m = min(CHUNK1, end - cs);
        if (t < m) ssrc[t] = g_esrc[cs + t];
        __syncthreads();
        if (t < 2 * m) {
            int e = t >> 1, hh = t & 1;
            int s = ssrc[e];
            float ea = g_as1[s * 2 + hh] + g_ad1[n * 2 + hh];
            ea = (ea > 0.f) ? ea : 0.2f * ea;
            sw[e * 2 + hh] = __expf(ea);
        }
        __syncthreads();
        for (int j = 0; j < m; j++) {
            float w = sw[j * 2 + h];
            acc += w * xh[(size_t)ssrc[j] * 256 + t];
            den += w;
        }
        __syncthreads();
    }
    float z = acc / (den + 1e-16f) + bias[t];
    g_z1[(size_t)n * 256 + t] = fmaxf(z, 0.f);   // fused ReLU
}

// ---------------- layer-2 aggregation (H=1, C=64): block=64 per node ---------
__global__ void k_agg2(const float* __restrict__ bias) {
    const float* __restrict__ xh = g_xh2;
    int n = blockIdx.x, t = threadIdx.x;      // t in [0,64)
    __shared__ int   ssrc[64];
    __shared__ float sw[64];
    float adh = g_ad2[n];
    int beg = g_rowptr[n], end = g_rowptr[n + 1];
    float acc = 0.f, den = 0.f;
    for (int cs = beg; cs < end; cs += 64) {
        int m = min(64, end - cs);
        if (t < m) {
            int s = g_esrc[cs + t];
            ssrc[t] = s;
            float ea = g_as2[s] + adh;
            ea = (ea > 0.f) ? ea : 0.2f * ea;
            sw[t] = __expf(ea);
        }
        __syncthreads();
        for (int j = 0; j < m; j++) {
            float w = sw[j];
            acc += w * xh[(size_t)ssrc[j] * 64 + t];
            den += w;
        }
        __syncthreads();
    }
    g_z2[(size_t)n * 64 + t] = acc / (den + 1e-16f) + bias[t];
}

// ---------------- decode: warp per edge, dot over 64 channels ----------------
__global__ void k_decode(int E, float* __restrict__ out) {
    const float* __restrict__ z = g_z2;
    int gid  = blockIdx.x * blockDim.x + threadIdx.x;
    int warp = gid >> 5;
    int lane = gid & 31;
    if (warp >= E) return;
    int s = g_src[warp];
    int d = g_dst[warp];
    const float* zs = z + (size_t)s * 64;
    const float* zd = z + (size_t)d * 64;
    float v = zs[lane] * zd[lane] + zs[lane + 32] * zd[lane + 32];
#pragma unroll
    for (int off = 16; off > 0; off >>= 1)
        v += __shfl_down_sync(0xFFFFFFFFu, v, off);
    if (lane == 0) out[warp] = v;
}

// ---------------- launch -----------------------------------------------------
extern "C" void kernel_launch(void* const* d_in, const int* in_sizes, int n_in,
                              void* d_out, int out_size) {
    const float* x   = (const float*)d_in[0];
    const void*  ei  = d_in[1];
    const float* W1  = (const float*)d_in[2];
    const float* as1 = (const float*)d_in[3];
    const float* ad1 = (const float*)d_in[4];
    const float* b1  = (const float*)d_in[5];
    const float* W2  = (const float*)d_in[6];
    const float* as2 = (const float*)d_in[7];
    const float* ad2 = (const float*)d_in[8];
    const float* b2  = (const float*)d_in[9];
    float*       out = (float*)d_out;

    const int N  = in_sizes[0] / 128;
    const int E  = out_size;          // one output per original edge (robust vs dtype)
    const int TE = E + N;

    // edge dtype detect + convert to int32 src/dst
    int nwords = 2 * E < 2048 ? 2 * E : 2048;
    k_detect<<<1, 256>>>((const unsigned*)ei, nwords);
    k_cvt<<<(E + 255) / 256, 256>>>(E, ei);

    // CSR by destination (shared by both layers; self-loops appended)
    k_zero_counts<<<(N + 255) / 256, 256>>>(N);
    k_hist<<<(TE + 255) / 256, 256>>>(E, N);
    k_scan<<<1, 1024>>>(N);
    k_scatter<<<(TE + 255) / 256, 256>>>(E, N);

    // layer 1
    k_sgemm<64, 64, 16, 4, 4, 0><<<dim3(4, (N + 63) / 64), 256>>>(N, 256, 128, x, W1);
    k_att<2, 128, 0><<<N, 256>>>(as1, ad1);
    k_agg1<<<N, 256>>>(b1);

    // layer 2
    k_sgemm<64, 64, 16, 4, 4, 1><<<dim3(1, (N + 63) / 64), 256>>>(N, 64, 256, nullptr, W2);
    k_att<1, 64, 1><<<N, 64>>>(as2, ad2);
    k_agg2<<<N, 64>>>(b2);

    // decode
    k_decode<<<(E * 32 + 255) / 256, 256>>>(E, out);
}

// round 5
// speedup vs baseline: 1.2240x; 1.2240x over previous
#include <cuda_runtime.h>
#include <cuda_bf16.h>
#include <cstdint>

#define NMAX 50000
#define EMAX 600000
#define TEMAX (EMAX + NMAX)

// ---------------- scratch (device globals; no allocation allowed) -------------
__device__ float g_xh1[(size_t)NMAX * 256];
__device__ float g_z1 [(size_t)NMAX * 256];
__device__ float g_xh2[(size_t)NMAX * 64];
__device__ float g_z2 [(size_t)NMAX * 64];
__device__ float g_as1[NMAX * 2];
__device__ float g_ad1[NMAX * 2];
__device__ float g_as2[NMAX];
__device__ float g_ad2[NMAX];
__device__ int   g_counts[NMAX];
__device__ int   g_cursor[NMAX];
__device__ int   g_rowptr[NMAX + 1];
__device__ int   g_esrc[TEMAX];
__device__ int   g_src[EMAX];
__device__ int   g_dst[EMAX];
__device__ int   g_is64;

// ---------------- edge dtype detect + convert --------------------------------
__global__ void k_detect(const unsigned* __restrict__ w, int nwords) {
    __shared__ int flag;
    if (threadIdx.x == 0) flag = 0;
    __syncthreads();
    for (int i = 1 + 2 * threadIdx.x; i < nwords; i += 2 * blockDim.x)
        if (w[i] != 0u) flag = 1;
    __syncthreads();
    if (threadIdx.x == 0) g_is64 = (flag == 0);
}

__global__ void k_cvt(int E, const void* __restrict__ p) {
    int e = blockIdx.x * blockDim.x + threadIdx.x;
    if (e >= E) return;
    if (g_is64) {
        const long long* q = (const long long*)p;
        g_src[e] = (int)q[e];
        g_dst[e] = (int)q[E + e];
    } else {
        const int* q = (const int*)p;
        g_src[e] = q[e];
        g_dst[e] = q[E + e];
    }
}

// ---------------- CSR build --------------------------------------------------
__global__ void k_zero_counts(int N) {
    int i = blockIdx.x * blockDim.x + threadIdx.x;
    if (i < N) g_counts[i] = 0;
}

__global__ void k_hist(int E, int N) {
    int i = blockIdx.x * blockDim.x + threadIdx.x;
    int TE = E + N;
    if (i >= TE) return;
    int dst = (i < E) ? g_dst[i] : (i - E);
    atomicAdd(&g_counts[dst], 1);
}

__global__ void k_scan(int N) {
    __shared__ int sh[1024];
    __shared__ int carry;
    int t = threadIdx.x;
    if (t == 0) carry = 0;
    __syncthreads();
    for (int base = 0; base < N; base += 1024) {
        int v = (base + t < N) ? g_counts[base + t] : 0;
        sh[t] = v;
        __syncthreads();
        for (int off = 1; off < 1024; off <<= 1) {
            int x = (t >= off) ? sh[t - off] : 0;
            __syncthreads();
            sh[t] += x;
            __syncthreads();
        }
        int incl = sh[t];
        if (base + t < N) {
            int excl = carry + incl - v;
            g_rowptr[base + t] = excl;
            g_cursor[base + t] = excl;
        }
        __syncthreads();
        if (t == 1023) carry += sh[1023];
        __syncthreads();
    }
    if (t == 0) g_rowptr[N] = carry;
}

__global__ void k_scatter(int E, int N) {
    int i = blockIdx.x * blockDim.x + threadIdx.x;
    int TE = E + N;
    if (i >= TE) return;
    int src, dst;
    if (i < E) { src = g_src[i]; dst = g_dst[i]; }
    else       { src = dst = i - E; }
    int pos = atomicAdd(&g_cursor[dst], 1);
    g_esrc[pos] = src;
}

// ---------------- GEMM1: C[M,256] = A[M,128] * B[128,256] --------------------
// 128x128x8 tiles, 256 threads, TM=TN=8, float4 loads, FFMA-bound.
__global__ __launch_bounds__(256) void k_gemm1(int M,
                                               const float* __restrict__ A,
                                               const float* __restrict__ B) {
    float* __restrict__ C = g_xh1;
    const int K = 128, N = 256;
    __shared__ float As[8][128];
    __shared__ float Bs[8][128];
    const int tid = threadIdx.x;
    const int tx = tid & 15;        // 0..15
    const int ty = tid >> 4;        // 0..15
    const int rowBase = blockIdx.y * 128;
    const int colBase = blockIdx.x * 128;

    // A load mapping: r = tid>>1 (0..127), c = (tid&1)*4
    const int ar = tid >> 1;
    const int ac = (tid & 1) * 4;
    // B load mapping: r = tid>>5 (0..7), c = (tid&31)*4
    const int br = tid >> 5;
    const int bc = (tid & 31) * 4;

    float acc[8][8];
#pragma unroll
    for (int i = 0; i < 8; i++)
#pragma unroll
        for (int j = 0; j < 8; j++) acc[i][j] = 0.f;

    for (int k0 = 0; k0 < K; k0 += 8) {
        // stage A (transposed)
        int gm = rowBase + ar;
        float4 av = (gm < M) ? *(const float4*)&A[(size_t)gm * K + k0 + ac]
                             : make_float4(0.f, 0.f, 0.f, 0.f);
        As[ac + 0][ar] = av.x;
        As[ac + 1][ar] = av.y;
        As[ac + 2][ar] = av.z;
        As[ac + 3][ar] = av.w;
        // stage B
        *(float4*)&Bs[br][bc] = *(const float4*)&B[(size_t)(k0 + br) * N + colBase + bc];
        __syncthreads();
#pragma unroll
        for (int kk = 0; kk < 8; kk++) {
            float4 a0 = *(float4*)&As[kk][ty * 8];
            float4 a1 = *(float4*)&As[kk][ty * 8 + 4];
            float4 b0 = *(float4*)&Bs[kk][tx * 8];
            float4 b1 = *(float4*)&Bs[kk][tx * 8 + 4];
            float ra[8] = {a0.x, a0.y, a0.z, a0.w, a1.x, a1.y, a1.z, a1.w};
            float rb[8] = {b0.x, b0.y, b0.z, b0.w, b1.x, b1.y, b1.z, b1.w};
#pragma unroll
            for (int i = 0; i < 8; i++)
#pragma unroll
                for (int j = 0; j < 8; j++) acc[i][j] += ra[i] * rb[j];
        }
        __syncthreads();
    }
#pragma unroll
    for (int i = 0; i < 8; i++) {
        int gm = rowBase + ty * 8 + i;
        if (gm >= M) continue;
        float* crow = &C[(size_t)gm * N + colBase + tx * 8];
        *(float4*)crow       = make_float4(acc[i][0], acc[i][1], acc[i][2], acc[i][3]);
        *(float4*)(crow + 4) = make_float4(acc[i][4], acc[i][5], acc[i][6], acc[i][7]);
    }
}

// ---------------- GEMM2: C[M,64] = g_z1[M,256] * B[256,64] -------------------
// 128x64x16 tiles, 256 threads, TM=8, TN=4.
__global__ __launch_bounds__(256) void k_gemm2(int M, const float* __restrict__ B) {
    const float* __restrict__ A = g_z1;
    float* __restrict__ C = g_xh2;
    const int K = 256, N = 64;
    __shared__ float As[16][128];
    __shared__ float Bs[16][64];
    const int tid = threadIdx.x;
    const int tx = tid & 15;        // 0..15 -> col block of 4
    const int ty = tid >> 4;        // 0..15 -> row block of 8
    const int rowBase = blockIdx.y * 128;

    // A tile: 128 rows x 16 cols = 512 float4s, 2 per thread
    // B tile: 16 rows x 64 cols = 256 float4s, 1 per thread
    const int br2 = tid >> 4;            // 0..15
    const int bc2 = (tid & 15) * 4;      // 0..60

    float acc[8][4];
#pragma unroll
    for (int i = 0; i < 8; i++)
#pragma unroll
        for (int j = 0; j < 4; j++) acc[i][j] = 0.f;

    for (int k0 = 0; k0 < K; k0 += 16) {
#pragma unroll
        for (int l = 0; l < 2; l++) {
            int idx = tid + l * 256;     // 0..511
            int r = idx >> 2;            // 0..127
            int c = (idx & 3) * 4;       // 0,4,8,12
            int gm = rowBase + r;
            float4 av = (gm < M) ? *(const float4*)&A[(size_t)gm * K + k0 + c]
                                 : make_float4(0.f, 0.f, 0.f, 0.f);
            As[c + 0][r] = av.x;
            As[c + 1][r] = av.y;
            As[c + 2][r] = av.z;
            As[c + 3][r] = av.w;
        }
        *(float4*)&Bs[br2][bc2] = *(const float4*)&B[(size_t)(k0 + br2) * N + bc2];
        __syncthreads();
#pragma unroll
        for (int kk = 0; kk < 16; kk++) {
            float4 a0 = *(float4*)&As[kk][ty * 8];
            float4 a1 = *(float4*)&As[kk][ty * 8 + 4];
            float4 b0 = *(float4*)&Bs[kk][tx * 4];
            float ra[8] = {a0.x, a0.y, a0.z, a0.w, a1.x, a1.y, a1.z, a1.w};
            float rb[4] = {b0.x, b0.y, b0.z, b0.w};
#pragma unroll
            for (int i = 0; i < 8; i++)
#pragma unroll
                for (int j = 0; j < 4; j++) acc[i][j] += ra[i] * rb[j];
        }
        __syncthreads();
    }
#pragma unroll
    for (int i = 0; i < 8; i++) {
        int gm = rowBase + ty * 8 + i;
        if (gm >= M) continue;
        *(float4*)&C[(size_t)gm * N + tx * 4] =
            make_float4(acc[i][0], acc[i][1], acc[i][2], acc[i][3]);
    }
}

// ---------------- attention logits -------------------------------------------
template<int H, int C, int MODE>
__global__ void k_att(const float* __restrict__ att_s,
                      const float* __restrict__ att_d) {
    const float* __restrict__ xh = (MODE == 0) ? g_xh1 : g_xh2;
    float* __restrict__ a_s = (MODE == 0) ? g_as1 : g_as2;
    float* __restrict__ a_d = (MODE == 0) ? g_ad1 : g_ad2;
    __shared__ float ss[256], sd[256];
    int n = blockIdx.x, t = threadIdx.x;
    const int HC = H * C;
    float v = xh[(size_t)n * HC + t];
    ss[t] = v * att_s[t];
    sd[t] = v * att_d[t];
    __syncthreads();
    for (int off = C / 2; off > 0; off >>= 1) {
        if ((t & (C - 1)) < off) { ss[t] += ss[t + off]; sd[t] += sd[t + off]; }
        __syncthreads();
    }
    if ((t & (C - 1)) == 0) {
        int h = t / C;
        a_s[n * H + h] = ss[t];
        a_d[n * H + h] = sd[t];
    }
}

// ---------------- layer-1 aggregation (H=2, C=128) ---------------------------
#define CHUNK1 64
__global__ void k_agg1(const float* __restrict__ bias) {
    const float* __restrict__ xh = g_xh1;
    int n = blockIdx.x, t = threadIdx.x;      // t in [0,256)
    int h = t >> 7;
    __shared__ int   ssrc[CHUNK1];
    __shared__ float sw[CHUNK1 * 2];
    int beg = g_rowptr[n], end = g_rowptr[n + 1];
    float acc = 0.f, den = 0.f;
    for (int cs = beg; cs < end; cs += CHUNK1) {
        int m = min(CHUNK1, end - cs);
        if (t < m) ssrc[t] = g_esrc[cs + t];
        __syncthreads();
        if (t < 2 * m) {
            int e = t >> 1, hh = t & 1;
            int s = ssrc[e];
            float ea = g_as1[s * 2 + hh] + g_ad1[n * 2 + hh];
            ea = (ea > 0.f) ? ea : 0.2f * ea;
            sw[e * 2 + hh] = __expf(ea);
        }
        __syncthreads();
        for (int j = 0; j < m; j++) {
            float w = sw[j * 2 + h];
            acc += w * xh[(size_t)ssrc[j] * 256 + t];
            den += w;
        }
        __syncthreads();
    }
    float z = acc / (den + 1e-16f) + bias[t];
    g_z1[(size_t)n * 256 + t] = fmaxf(z, 0.f);   // fused ReLU
}

// ---------------- layer-2 aggregation (H=1, C=64) ----------------------------
__global__ void k_agg2(const float* __restrict__ bias) {
    const float* __restrict__ xh = g_xh2;
    int n = blockIdx.x, t = threadIdx.x;      // t in [0,64)
    __shared__ int   ssrc[64];
    __shared__ float sw[64];
    float adh = g_ad2[n];
    int beg = g_rowptr[n], end = g_rowptr[n + 1];
    float acc = 0.f, den = 0.f;
    for (int cs = beg; cs < end; cs += 64) {
        int m = min(64, end - cs);
        if (t < m) {
            int s = g_esrc[cs + t];
            ssrc[t] = s;
            float ea = g_as2[s] + adh;
            ea = (ea > 0.f) ? ea : 0.2f * ea;
            sw[t] = __expf(ea);
        }
        __syncthreads();
        for (int j = 0; j < m; j++) {
            float w = sw[j];
            acc += w * xh[(size_t)ssrc[j] * 64 + t];
            den += w;
        }
        __syncthreads();
    }
    g_z2[(size_t)n * 64 + t] = acc / (den + 1e-16f) + bias[t];
}

// ---------------- decode: warp per edge, dot over 64 channels ----------------
__global__ void k_decode(int E, float* __restrict__ out) {
    const float* __restrict__ z = g_z2;
    int gid  = blockIdx.x * blockDim.x + threadIdx.x;
    int warp = gid >> 5;
    int lane = gid & 31;
    if (warp >= E) return;
    int s = g_src[warp];
    int d = g_dst[warp];
    const float* zs = z + (size_t)s * 64;
    const float* zd = z + (size_t)d * 64;
    float v = zs[lane] * zd[lane] + zs[lane + 32] * zd[lane + 32];
#pragma unroll
    for (int off = 16; off > 0; off >>= 1)
        v += __shfl_down_sync(0xFFFFFFFFu, v, off);
    if (lane == 0) out[warp] = v;
}

// ---------------- launch -----------------------------------------------------
extern "C" void kernel_launch(void* const* d_in, const int* in_sizes, int n_in,
                              void* d_out, int out_size) {
    const float* x   = (const float*)d_in[0];
    const void*  ei  = d_in[1];
    const float* W1  = (const float*)d_in[2];
    const float* as1 = (const float*)d_in[3];
    const float* ad1 = (const float*)d_in[4];
    const float* b1  = (const float*)d_in[5];
    const float* W2  = (const float*)d_in[6];
    const float* as2 = (const float*)d_in[7];
    const float* ad2 = (const float*)d_in[8];
    const float* b2  = (const float*)d_in[9];
    float*       out = (float*)d_out;

    const int N  = in_sizes[0] / 128;
    const int E  = out_size;
    const int TE = E + N;

    // edge dtype detect + convert to int32 src/dst
    int nwords = 2 * E < 2048 ? 2 * E : 2048;
    k_detect<<<1, 256>>>((const unsigned*)ei, nwords);
    k_cvt<<<(E + 255) / 256, 256>>>(E, ei);

    // CSR by destination (shared by both layers; self-loops appended)
    k_zero_counts<<<(N + 255) / 256, 256>>>(N);
    k_hist<<<(TE + 255) / 256, 256>>>(E, N);
    k_scan<<<1, 1024>>>(N);
    k_scatter<<<(TE + 255) / 256, 256>>>(E, N);

    // layer 1
    k_gemm1<<<dim3(2, (N + 127) / 128), 256>>>(N, x, W1);
    k_att<2, 128, 0><<<N, 256>>>(as1, ad1);
    k_agg1<<<N, 256>>>(b1);

    // layer 2
    k_gemm2<<<dim3(1, (N + 127) / 128), 256>>>(N, W2);
    k_att<1, 64, 1><<<N, 64>>>(as2, ad2);
    k_agg2<<<N, 64>>>(b2);

    // decode
    k_decode<<<(E * 32 + 255) / 256, 256>>>(E, out);
}

// round 7
// speedup vs baseline: 1.7520x; 1.4314x over previous
#include <cuda_runtime.h>
#include <cuda_bf16.h>
#include <cstdint>

#define NMAX 50000
#define EMAX 600000
#define TEMAX (EMAX + NMAX)

// ---------------- scratch (device globals; no allocation allowed) -------------
__device__ float g_xh1[(size_t)NMAX * 256];
__device__ float g_z1 [(size_t)NMAX * 256];
__device__ float g_xh2[(size_t)NMAX * 64];
__device__ float g_z2 [(size_t)NMAX * 64];
__device__ float g_as1[NMAX * 2];
__device__ float g_ad1[NMAX * 2];
__device__ float g_as2[NMAX];
__device__ float g_ad2[NMAX];
__device__ int   g_counts[NMAX];
__device__ int   g_cursor[NMAX];
__device__ int   g_rowptr[NMAX + 1];
__device__ int   g_esrc[TEMAX];
__device__ int   g_src[EMAX];
__device__ int   g_dst[EMAX];
__device__ int   g_is64;
__device__ int   g_bsums[256];
__device__ int   g_boff[256];

// ---------------- edge dtype detect ------------------------------------------
__global__ void k_detect(const unsigned* __restrict__ w, int nwords) {
    __shared__ int flag;
    if (threadIdx.x == 0) flag = 0;
    __syncthreads();
    for (int i = 1 + 2 * threadIdx.x; i < nwords; i += 2 * blockDim.x)
        if (w[i] != 0u) flag = 1;
    __syncthreads();
    if (threadIdx.x == 0) g_is64 = (flag == 0);
}

// counts start at 1: self-loop folded in
__global__ void k_init_counts(int N) {
    int i = blockIdx.x * blockDim.x + threadIdx.x;
    if (i < N) g_counts[i] = 1;
}

// convert edges to int32 + histogram dst
__global__ void k_cvt_hist(int E, const void* __restrict__ p) {
    int e = blockIdx.x * blockDim.x + threadIdx.x;
    if (e >= E) return;
    int s, d;
    if (g_is64) {
        const long long* q = (const long long*)p;
        s = (int)q[e];
        d = (int)q[E + e];
    } else {
        const int* q = (const int*)p;
        s = q[e];
        d = q[E + e];
    }
    g_src[e] = s;
    g_dst[e] = d;
    atomicAdd(&g_counts[d], 1);
}

// ---------------- parallel scan (3 kernels) -----------------------------------
__global__ void k_bsum(int N) {
    int t = threadIdx.x;
    int i = blockIdx.x * 256 + t;
    int v = (i < N) ? g_counts[i] : 0;
#pragma unroll
    for (int off = 16; off > 0; off >>= 1)
        v += __shfl_down_sync(0xFFFFFFFFu, v, off);
    __shared__ int sh[8];
    if ((t & 31) == 0) sh[t >> 5] = v;
    __syncthreads();
    if (t < 8) {
        int x = sh[t];
#pragma unroll
        for (int off = 4; off > 0; off >>= 1)
            x += __shfl_down_sync(0xFFu, x, off);
        if (t == 0) g_bsums[blockIdx.x] = x;
    }
}

__global__ void k_scan_sums(int nb, int N) {
    __shared__ int sh[256];
    int t = threadIdx.x;
    int v = (t < nb) ? g_bsums[t] : 0;
    sh[t] = v;
    __syncthreads();
#pragma unroll
    for (int off = 1; off < 256; off <<= 1) {
        int x = (t >= off) ? sh[t - off] : 0;
        __syncthreads();
        sh[t] += x;
        __syncthreads();
    }
    if (t < nb) g_boff[t] = sh[t] - v;
    if (t == 255) g_rowptr[N] = sh[255];
}

__global__ void k_scan_apply(int N) {
    __shared__ int sh[256];
    int t = threadIdx.x;
    int i = blockIdx.x * 256 + t;
    int v = (i < N) ? g_counts[i] : 0;
    sh[t] = v;
    __syncthreads();
#pragma unroll
    for (int off = 1; off < 256; off <<= 1) {
        int x = (t >= off) ? sh[t - off] : 0;
        __syncthreads();
        sh[t] += x;
        __syncthreads();
    }
    if (i < N) {
        int excl = sh[t] - v + g_boff[blockIdx.x];
        g_rowptr[i] = excl;
        g_cursor[i] = excl;
    }
}

__global__ void k_scatter(int E, int N) {
    int i = blockIdx.x * blockDim.x + threadIdx.x;
    int TE = E + N;
    if (i >= TE) return;
    int src, dst;
    if (i < E) { src = g_src[i]; dst = g_dst[i]; }
    else       { src = dst = i - E; }
    int pos = atomicAdd(&g_cursor[dst], 1);
    g_esrc[pos] = src;
}

// ---------------- tf32 mma.sync GEMM ------------------------------------------
__device__ __forceinline__ uint32_t f2tf(float f) {
    uint32_t u;
    asm("cvt.rna.tf32.f32 %0, %1;" : "=r"(u) : "f"(f));
    return u;
}

__device__ __forceinline__ void mma_tf32(float* c, const uint32_t* a, const uint32_t* b) {
    asm volatile(
        "mma.sync.aligned.m16n8k8.row.col.f32.tf32.tf32.f32 "
        "{%0,%1,%2,%3}, {%4,%5,%6,%7}, {%8,%9}, {%0,%1,%2,%3};"
        : "+f"(c[0]), "+f"(c[1]), "+f"(c[2]), "+f"(c[3])
        : "r"(a[0]), "r"(a[1]), "r"(a[2]), "r"(a[3]), "r"(b[0]), "r"(b[1]));
}

// C[M,NN] = A[M,K] * B[K,NN]; tiles BM=128 x BN x BK=32; 8 warps (2m x 4n).
// MODE 0: A=param, C=g_xh1; MODE 1: A=g_z1, C=g_xh2.
template<int BN, int K, int NN, int MODE>
__global__ __launch_bounds__(256) void k_mma(int M,
                                             const float* __restrict__ Ain,
                                             const float* __restrict__ B) {
    const float* __restrict__ A = (MODE == 0) ? Ain : g_z1;
    float* __restrict__ C = (MODE == 0) ? g_xh1 : g_xh2;
    constexpr int NF = BN / 32;         // n-frags per warp (BN/4 cols / 8)
    __shared__ uint32_t As[128][36];    // [m][k], pad 4 -> conflict-free frag reads
    __shared__ uint32_t Bs[32][BN + 8]; // [k][n], pad 8 -> conflict-free frag reads

    const int tid  = threadIdx.x;
    const int lane = tid & 31;
    const int wid  = tid >> 5;
    const int g    = lane >> 2;     // 0..7
    const int tg   = lane & 3;      // 0..3
    const int wm   = (wid & 1) * 64;
    const int wn   = (wid >> 1) * (BN / 4);
    const int rowBase = blockIdx.y * 128;
    const int colBase = blockIdx.x * BN;

    float acc[4][NF][4];
#pragma unroll
    for (int i = 0; i < 4; i++)
#pragma unroll
        for (int j = 0; j < NF; j++)
#pragma unroll
            for (int q = 0; q < 4; q++) acc[i][j][q] = 0.f;

    for (int k0 = 0; k0 < K; k0 += 32) {
        // stage A: 128x32 floats = 1024 float4, 4 per thread
#pragma unroll
        for (int l = 0; l < 4; l++) {
            int idx = tid + l * 256;
            int r = idx >> 3;             // 0..127
            int c = (idx & 7) * 4;        // 0..28
            int gm = rowBase + r;
            float4 av = (gm < M) ? *(const float4*)&A[(size_t)gm * K + k0 + c]
                                 : make_float4(0.f, 0.f, 0.f, 0.f);
            uint4 tv = make_uint4(f2tf(av.x), f2tf(av.y), f2tf(av.z), f2tf(av.w));
            *(uint4*)&As[r][c] = tv;
        }
        // stage B: 32xBN floats
#pragma unroll
        for (int idx = tid; idx < 32 * BN / 4; idx += 256) {
            int r = idx / (BN / 4);
            int c = (idx % (BN / 4)) * 4;
            float4 bv = *(const float4*)&B[(size_t)(k0 + r) * NN + colBase + c];
            uint4 tv = make_uint4(f2tf(bv.x), f2tf(bv.y), f2tf(bv.z), f2tf(bv.w));
            *(uint4*)&Bs[r][c] = tv;
        }
        __syncthreads();
#pragma unroll
        for (int kk = 0; kk < 4; kk++) {
            const int k = kk * 8;
            uint32_t a[4][4];
#pragma unroll
            for (int i = 0; i < 4; i++) {
                int m0 = wm + i * 16;
                a[i][0] = As[m0 + g][k + tg];
                a[i][1] = As[m0 + 8 + g][k + tg];
                a[i][2] = As[m0 + g][k + 4 + tg];
                a[i][3] = As[m0 + 8 + g][k + 4 + tg];
            }
            uint32_t b[NF][2];
#pragma unroll
            for (int j = 0; j < NF; j++) {
                int n0 = wn + j * 8;
                b[j][0] = Bs[k + tg][n0 + g];
                b[j][1] = Bs[k + 4 + tg][n0 + g];
            }
#pragma unroll
            for (int i = 0; i < 4; i++)
#pragma unroll
                for (int j = 0; j < NF; j++)
                    mma_tf32(acc[i][j], a[i], b[j]);
        }
        __syncthreads();
    }
    // epilogue
#pragma unroll
    for (int i = 0; i < 4; i++) {
        int row0 = rowBase + wm + i * 16 + g;
        int row1 = row0 + 8;
#pragma unroll
        for (int j = 0; j < NF; j++) {
            int col = colBase + wn + j * 8 + 2 * tg;
            if (row0 < M)
                *(float2*)&C[(size_t)row0 * NN + col] = make_float2(acc[i][j][0], acc[i][j][1]);
            if (row1 < M)
                *(float2*)&C[(size_t)row1 * NN + col] = make_float2(acc[i][j][2], acc[i][j][3]);
        }
    }
}

// ---------------- attention logits -------------------------------------------
template<int H, int C, int MODE>
__global__ void k_att(const float* __restrict__ att_s,
                      const float* __restrict__ att_d) {
    const float* __restrict__ xh = (MODE == 0) ? g_xh1 : g_xh2;
    float* __restrict__ a_s = (MODE == 0) ? g_as1 : g_as2;
    float* __restrict__ a_d = (MODE == 0) ? g_ad1 : g_ad2;
    __shared__ float ss[256], sd[256];
    int n = blockIdx.x, t = threadIdx.x;
    const int HC = H * C;
    float v = xh[(size_t)n * HC + t];
    ss[t] = v * att_s[t];
    sd[t] = v * att_d[t];
    __syncthreads();
    for (int off = C / 2; off > 0; off >>= 1) {
        if ((t & (C - 1)) < off) { ss[t] += ss[t + off]; sd[t] += sd[t + off]; }
        __syncthreads();
    }
    if ((t & (C - 1)) == 0) {
        int h = t / C;
        a_s[n * H + h] = ss[t];
        a_d[n * H + h] = sd[t];
    }
}

// ---------------- layer-1 aggregation (H=2, C=128) ---------------------------
#define CHUNK1 64
__global__ void k_agg1(const float* __restrict__ bias) {
    const float* __restrict__ xh = g_xh1;
    int n = blockIdx.x, t = threadIdx.x;      // t in [0,256)
    int h = t >> 7;
    __shared__ int   ssrc[CHUNK1];
    __shared__ float sw[CHUNK1 * 2];
    int beg = g_rowptr[n], end = g_rowptr[n + 1];
    float acc = 0.f, den = 0.f;
    for (int cs = beg; cs < end; cs += CHUNK1) {
        int m = min(CHUNK1, end - cs);
        if (t < m) ssrc[t] = g_esrc[cs + t];
        __syncthreads();
        if (t < 2 * m) {
            int e = t >> 1, hh = t & 1;
            int s = ssrc[e];
            float ea = g_as1[s * 2 + hh] + g_ad1[n * 2 + hh];
            ea = (ea > 0.f) ? ea : 0.2f * ea;
            sw[e * 2 + hh] = __expf(ea);
        }
        __syncthreads();
        for (int j = 0; j < m; j++) {
            float w = sw[j * 2 + h];
            acc += w * xh[(size_t)ssrc[j] * 256 + t];
            den += w;
        }
        __syncthreads();
    }
    float z = acc / (den + 1e-16f) + bias[t];
    g_z1[(size_t)n * 256 + t] = fmaxf(z, 0.f);   // fused ReLU
}

// ---------------- layer-2 aggregation (H=1, C=64) ----------------------------
__global__ void k_agg2(const float* __restrict__ bias) {
    const float* __restrict__ xh = g_xh2;
    int n = blockIdx.x, t = threadIdx.x;      // t in [0,64)
    __shared__ int   ssrc[64];
    __shared__ float sw[64];
    float adh = g_ad2[n];
    int beg = g_rowptr[n], end = g_rowptr[n + 1];
    float acc = 0.f, den = 0.f;
    for (int cs = beg; cs < end; cs += 64) {
        int m = min(64, end - cs);
        if (t < m) {
            int s = g_esrc[cs + t];
            ssrc[t] = s;
            float ea = g_as2[s] + adh;
            ea = (ea > 0.f) ? ea : 0.2f * ea;
            sw[t] = __expf(ea);
        }
        __syncthreads();
        for (int j = 0; j < m; j++) {
            float w = sw[j];
            acc += w * xh[(size_t)ssrc[j] * 64 + t];
            den += w;
        }
        __syncthreads();
    }
    g_z2[(size_t)n * 64 + t] = acc / (den + 1e-16f) + bias[t];
}

// ---------------- decode: warp per edge, dot over 64 channels ----------------
__global__ void k_decode(int E, float* __restrict__ out) {
    const float* __restrict__ z = g_z2;
    int gid  = blockIdx.x * blockDim.x + threadIdx.x;
    int warp = gid >> 5;
    int lane = gid & 31;
    if (warp >= E) return;
    int s = g_src[warp];
    int d = g_dst[warp];
    const float* zs = z + (size_t)s * 64;
    const float* zd = z + (size_t)d * 64;
    float v = zs[lane] * zd[lane] + zs[lane + 32] * zd[lane + 32];
#pragma unroll
    for (int off = 16; off > 0; off >>= 1)
        v += __shfl_down_sync(0xFFFFFFFFu, v, off);
    if (lane == 0) out[warp] = v;
}

// ---------------- launch -----------------------------------------------------
extern "C" void kernel_launch(void* const* d_in, const int* in_sizes, int n_in,
                              void* d_out, int out_size) {
    const float* x   = (const float*)d_in[0];
    const void*  ei  = d_in[1];
    const float* W1  = (const float*)d_in[2];
    const float* as1 = (const float*)d_in[3];
    const float* ad1 = (const float*)d_in[4];
    const float* b1  = (const float*)d_in[5];
    const float* W2  = (const float*)d_in[6];
    const float* as2 = (const float*)d_in[7];
    const float* ad2 = (const float*)d_in[8];
    const float* b2  = (const float*)d_in[9];
    float*       out = (float*)d_out;

    const int N  = in_sizes[0] / 128;
    const int E  = out_size;
    const int TE = E + N;
    const int nb = (N + 255) / 256;

    // edge dtype detect + convert + hist (self-loops folded into init)
    int nwords = 2 * E < 2048 ? 2 * E : 2048;
    k_detect<<<1, 256>>>((const unsigned*)ei, nwords);
    k_init_counts<<<nb, 256>>>(N);
    k_cvt_hist<<<(E + 255) / 256, 256>>>(E, ei);

    // parallel exclusive scan -> rowptr/cursor
    k_bsum<<<nb, 256>>>(N);
    k_scan_sums<<<1, 256>>>(nb, N);
    k_scan_apply<<<nb, 256>>>(N);
    k_scatter<<<(TE + 255) / 256, 256>>>(E, N);

    // layer 1
    k_mma<128, 128, 256, 0><<<dim3(2, (N + 127) / 128), 256>>>(N, x, W1);
    k_att<2, 128, 0><<<N, 256>>>(as1, ad1);
    k_agg1<<<N, 256>>>(b1);

    // layer 2
    k_mma<64, 256, 64, 1><<<dim3(1, (N + 127) / 128), 256>>>(N, nullptr, W2);
    k_att<1, 64, 1><<<N, 64>>>(as2, ad2);
    k_agg2<<<N, 64>>>(b2);

    // decode
    k_decode<<<(E * 32 + 255) / 256, 256>>>(E, out);
}

// round 12
// speedup vs baseline: 2.3324x; 1.3313x over previous
#include <cuda_runtime.h>
#include <cuda_bf16.h>
#include <cstdint>

#define NMAX 50000
#define EMAX 600000
#define TEMAX (EMAX + NMAX)

// ---------------- scratch (device globals; no allocation allowed) -------------
__device__ float g_xh1[(size_t)NMAX * 256];
__device__ float g_z1 [(size_t)NMAX * 256];
__device__ float g_xh2[(size_t)NMAX * 64];
__device__ float g_z2 [(size_t)NMAX * 64];
__device__ float g_as1[NMAX * 2];
__device__ float g_ad1[NMAX * 2];
__device__ float g_as2[NMAX];
__device__ float g_ad2[NMAX];
__device__ int   g_counts[NMAX];
__device__ int   g_cursor[NMAX];
__device__ int   g_rowptr[NMAX + 1];
__device__ int   g_esrc[TEMAX];
__device__ int   g_src[EMAX];
__device__ int   g_dst[EMAX];
__device__ int   g_is64;
__device__ int   g_bsums[256];
__device__ int   g_boff[256];

// ---------------- edge dtype detect ------------------------------------------
__global__ void k_detect(const unsigned* __restrict__ w, int nwords) {
    __shared__ int flag;
    if (threadIdx.x == 0) flag = 0;
    __syncthreads();
    for (int i = 1 + 2 * threadIdx.x; i < nwords; i += 2 * blockDim.x)
        if (w[i] != 0u) flag = 1;
    __syncthreads();
    if (threadIdx.x == 0) g_is64 = (flag == 0);
}

// counts start at 1: self-loop folded in
__global__ void k_init_counts(int N) {
    int i = blockIdx.x * blockDim.x + threadIdx.x;
    if (i < N) g_counts[i] = 1;
}

// convert edges to int32 + histogram dst
__global__ void k_cvt_hist(int E, const void* __restrict__ p) {
    int e = blockIdx.x * blockDim.x + threadIdx.x;
    if (e >= E) return;
    int s, d;
    if (g_is64) {
        const long long* q = (const long long*)p;
        s = (int)q[e];
        d = (int)q[E + e];
    } else {
        const int* q = (const int*)p;
        s = q[e];
        d = q[E + e];
    }
    g_src[e] = s;
    g_dst[e] = d;
    atomicAdd(&g_counts[d], 1);
}

// ---------------- parallel scan (3 kernels) -----------------------------------
__global__ void k_bsum(int N) {
    int t = threadIdx.x;
    int i = blockIdx.x * 256 + t;
    int v = (i < N) ? g_counts[i] : 0;
#pragma unroll
    for (int off = 16; off > 0; off >>= 1)
        v += __shfl_down_sync(0xFFFFFFFFu, v, off);
    __shared__ int sh[8];
    if ((t & 31) == 0) sh[t >> 5] = v;
    __syncthreads();
    if (t < 8) {
        int x = sh[t];
#pragma unroll
        for (int off = 4; off > 0; off >>= 1)
            x += __shfl_down_sync(0xFFu, x, off);
        if (t == 0) g_bsums[blockIdx.x] = x;
    }
}

__global__ void k_scan_sums(int nb, int N) {
    __shared__ int sh[256];
    int t = threadIdx.x;
    int v = (t < nb) ? g_bsums[t] : 0;
    sh[t] = v;
    __syncthreads();
#pragma unroll
    for (int off = 1; off < 256; off <<= 1) {
        int x = (t >= off) ? sh[t - off] : 0;
        __syncthreads();
        sh[t] += x;
        __syncthreads();
    }
    if (t < nb) g_boff[t] = sh[t] - v;
    if (t == 255) g_rowptr[N] = sh[255];
}

__global__ void k_scan_apply(int N) {
    __shared__ int sh[256];
    int t = threadIdx.x;
    int i = blockIdx.x * 256 + t;
    int v = (i < N) ? g_counts[i] : 0;
    sh[t] = v;
    __syncthreads();
#pragma unroll
    for (int off = 1; off < 256; off <<= 1) {
        int x = (t >= off) ? sh[t - off] : 0;
        __syncthreads();
        sh[t] += x;
        __syncthreads();
    }
    if (i < N) {
        int excl = sh[t] - v + g_boff[blockIdx.x];
        g_rowptr[i] = excl;
        g_cursor[i] = excl;
    }
}

__global__ void k_scatter(int E, int N) {
    int i = blockIdx.x * blockDim.x + threadIdx.x;
    int TE = E + N;
    if (i >= TE) return;
    int src, dst;
    if (i < E) { src = g_src[i]; dst = g_dst[i]; }
    else       { src = dst = i - E; }
    int pos = atomicAdd(&g_cursor[dst], 1);
    g_esrc[pos] = src;
}

// ---------------- tf32 mma.sync GEMM + fused att logits -----------------------
__device__ __forceinline__ uint32_t f2tf(float f) {
    uint32_t u;
    asm("cvt.rna.tf32.f32 %0, %1;" : "=r"(u) : "f"(f));
    return u;
}

__device__ __forceinline__ void mma_tf32(float* c, const uint32_t* a, const uint32_t* b) {
    asm volatile(
        "mma.sync.aligned.m16n8k8.row.col.f32.tf32.tf32.f32 "
        "{%0,%1,%2,%3}, {%4,%5,%6,%7}, {%8,%9}, {%0,%1,%2,%3};"
        : "+f"(c[0]), "+f"(c[1]), "+f"(c[2]), "+f"(c[3])
        : "r"(a[0]), "r"(a[1]), "r"(a[2]), "r"(a[3]), "r"(b[0]), "r"(b[1]));
}

// C[M,NN] = A[M,K] * B[K,NN]; BM=128 x BN x BK=32; 8 warps (2m x 4n).
// RN tf32 conversion at stage time (correctness-critical vs RZ truncation).
// Epilogue computes complete a_src/a_dst for this block's rows.
// MODE 0: A=param, C=g_xh1, att->g_as1/g_ad1 (head=colBase>>7, H=2)
// MODE 1: A=g_z1,  C=g_xh2, att->g_as2/g_ad2 (H=1)
template<int BN, int K, int NN, int MODE>
__global__ __launch_bounds__(256) void k_mma(int M,
                                             const float* __restrict__ Ain,
                                             const float* __restrict__ B,
                                             const float* __restrict__ att_s,
                                             const float* __restrict__ att_d) {
    const float* __restrict__ A = (MODE == 0) ? Ain : g_z1;
    float* __restrict__ C = (MODE == 0) ? g_xh1 : g_xh2;
    constexpr int NF = BN / 32;         // n-frags per warp
    __shared__ uint32_t As[128][36];    // [m][k], pad 4
    __shared__ uint32_t Bs[32][BN + 8]; // [k][n], pad 8
    __shared__ float s_part[4][128][2];

    const int tid  = threadIdx.x;
    const int lane = tid & 31;
    const int wid  = tid >> 5;
    const int g    = lane >> 2;     // 0..7
    const int tg   = lane & 3;      // 0..3
    const int wm   = (wid & 1) * 64;
    const int wn   = (wid >> 1) * (BN / 4);
    const int rowBase = blockIdx.y * 128;
    const int colBase = blockIdx.x * BN;

    float acc[4][NF][4];
#pragma unroll
    for (int i = 0; i < 4; i++)
#pragma unroll
        for (int j = 0; j < NF; j++)
#pragma unroll
            for (int q = 0; q < 4; q++) acc[i][j][q] = 0.f;

    for (int k0 = 0; k0 < K; k0 += 32) {
        // stage A: 128x32 floats = 1024 float4, 4 per thread (RN tf32 convert)
#pragma unroll
        for (int l = 0; l < 4; l++) {
            int idx = tid + l * 256;
            int r = idx >> 3;             // 0..127
            int c = (idx & 7) * 4;        // 0..28
            int gm = rowBase + r;
            float4 av = (gm < M) ? *(const float4*)&A[(size_t)gm * K + k0 + c]
                                 : make_float4(0.f, 0.f, 0.f, 0.f);
            uint4 tv = make_uint4(f2tf(av.x), f2tf(av.y), f2tf(av.z), f2tf(av.w));
            *(uint4*)&As[r][c] = tv;
        }
        // stage B: 32xBN floats
#pragma unroll
        for (int idx = tid; idx < 32 * BN / 4; idx += 256) {
            int r = idx / (BN / 4);
            int c = (idx % (BN / 4)) * 4;
            float4 bv = *(const float4*)&B[(size_t)(k0 + r) * NN + colBase + c];
            uint4 tv = make_uint4(f2tf(bv.x), f2tf(bv.y), f2tf(bv.z), f2tf(bv.w));
            *(uint4*)&Bs[r][c] = tv;
        }
        __syncthreads();
#pragma unroll
        for (int kk = 0; kk < 4; kk++) {
            const int k = kk * 8;
            uint32_t a[4][4];
#pragma unroll
            for (int i = 0; i < 4; i++) {
                int m0 = wm + i * 16;
                a[i][0] = As[m0 + g][k + tg];
                a[i][1] = As[m0 + 8 + g][k + tg];
                a[i][2] = As[m0 + g][k + 4 + tg];
                a[i][3] = As[m0 + 8 + g][k + 4 + tg];
            }
            uint32_t b[NF][2];
#pragma unroll
            for (int j = 0; j < NF; j++) {
                int n0 = wn + j * 8;
                b[j][0] = Bs[k + tg][n0 + g];
                b[j][1] = Bs[k + 4 + tg][n0 + g];
            }
#pragma unroll
            for (int i = 0; i < 4; i++)
#pragma unroll
                for (int j = 0; j < NF; j++)
                    mma_tf32(acc[i][j], a[i], b[j]);
        }
        __syncthreads();
    }

    // epilogue: store C + fused attention-logit reduction
    float atsv[NF][2], atdv[NF][2];
#pragma unroll
    for (int j = 0; j < NF; j++) {
        int col = colBase + wn + j * 8 + 2 * tg;
        atsv[j][0] = att_s[col];     atsv[j][1] = att_s[col + 1];
        atdv[j][0] = att_d[col];     atdv[j][1] = att_d[col + 1];
    }

    float rps[8], rpd[8];   // per (i, half) row partials
#pragma unroll
    for (int i = 0; i < 4; i++) {
        int row0 = rowBase + wm + i * 16 + g;
        int row1 = row0 + 8;
        float ps0 = 0.f, pd0 = 0.f, ps1 = 0.f, pd1 = 0.f;
#pragma unroll
        for (int j = 0; j < NF; j++) {
            ps0 += acc[i][j][0] * atsv[j][0] + acc[i][j][1] * atsv[j][1];
            pd0 += acc[i][j][0] * atdv[j][0] + acc[i][j][1] * atdv[j][1];
            ps1 += acc[i][j][2] * atsv[j][0] + acc[i][j][3] * atsv[j][1];
            pd1 += acc[i][j][2] * atdv[j][0] + acc[i][j][3] * atdv[j][1];
            int col = colBase + wn + j * 8 + 2 * tg;
            if (row0 < M)
                *(float2*)&C[(size_t)row0 * NN + col] = make_float2(acc[i][j][0], acc[i][j][1]);
            if (row1 < M)
                *(float2*)&C[(size_t)row1 * NN + col] = make_float2(acc[i][j][2], acc[i][j][3]);
        }
        rps[2 * i] = ps0; rpd[2 * i] = pd0;
        rps[2 * i + 1] = ps1; rpd[2 * i + 1] = pd1;
    }
    // reduce over tg (4 adjacent lanes share g)
#pragma unroll
    for (int q = 0; q < 8; q++) {
        rps[q] += __shfl_xor_sync(0xFFFFFFFFu, rps[q], 1);
        rps[q] += __shfl_xor_sync(0xFFFFFFFFu, rps[q], 2);
        rpd[q] += __shfl_xor_sync(0xFFFFFFFFu, rpd[q], 1);
        rpd[q] += __shfl_xor_sync(0xFFFFFFFFu, rpd[q], 2);
    }
    const int warpN = wid >> 1;
    if (tg == 0) {
#pragma unroll
        for (int i = 0; i < 4; i++) {
            int rl0 = wm + i * 16 + g;
            s_part[warpN][rl0][0] = rps[2 * i];
            s_part[warpN][rl0][1] = rpd[2 * i];
            s_part[warpN][rl0 + 8][0] = rps[2 * i + 1];
            s_part[warpN][rl0 + 8][1] = rpd[2 * i + 1];
        }
    }
    __syncthreads();
    if (tid < 128) {
        int row = rowBase + tid;
        if (row < M) {
            float vs = 0.f, vd = 0.f;
#pragma unroll
            for (int w = 0; w < 4; w++) {
                vs += s_part[w][tid][0];
                vd += s_part[w][tid][1];
            }
            if (MODE == 0) {
                int head = colBase >> 7;
                g_as1[row * 2 + head] = vs;
                g_ad1[row * 2 + head] = vd;
            } else {
                g_as2[row] = vs;
                g_ad2[row] = vd;
            }
        }
    }
}

// ---------------- layer-1 aggregation (H=2, C=128) ---------------------------
#define CHUNK1 64
__global__ void k_agg1(const float* __restrict__ bias) {
    const float* __restrict__ xh = g_xh1;
    int n = blockIdx.x, t = threadIdx.x;      // t in [0,256)
    int h = t >> 7;
    __shared__ int   ssrc[CHUNK1];
    __shared__ float sw[CHUNK1 * 2];
    int beg = g_rowptr[n], end = g_rowptr[n + 1];
    float acc = 0.f, den = 0.f;
    for (int cs = beg; cs < end; cs += CHUNK1) {
        int m = min(CHUNK1, end - cs);
        if (t < m) ssrc[t] = g_esrc[cs + t];
        __syncthreads();
        if (t < 2 * m) {
            int e = t >> 1, hh = t & 1;
            int s = ssrc[e];
            float ea = g_as1[s * 2 + hh] + g_ad1[n * 2 + hh];
            ea = (ea > 0.f) ? ea : 0.2f * ea;
            sw[e * 2 + hh] = __expf(ea);
        }
        __syncthreads();
        for (int j = 0; j < m; j++) {
            float w = sw[j * 2 + h];
            acc += w * xh[(size_t)ssrc[j] * 256 + t];
            den += w;
        }
        __syncthreads();
    }
    float z = acc / (den + 1e-16f) + bias[t];
    g_z1[(size_t)n * 256 + t] = fmaxf(z, 0.f);   // fused ReLU
}

// ---------------- layer-2 aggregation (H=1, C=64) ----------------------------
__global__ void k_agg2(const float* __restrict__ bias) {
    const float* __restrict__ xh = g_xh2;
    int n = blockIdx.x, t = threadIdx.x;      // t in [0,64)
    __shared__ int   ssrc[64];
    __shared__ float sw[64];
    float adh = g_ad2[n];
    int beg = g_rowptr[n], end = g_rowptr[n + 1];
    float acc = 0.f, den = 0.f;
    for (int cs = beg; cs < end; cs += 64) {
        int m = min(64, end - cs);
        if (t < m) {
            int s = g_esrc[cs + t];
            ssrc[t] = s;
            float ea = g_as2[s] + adh;
            ea = (ea > 0.f) ? ea : 0.2f * ea;
            sw[t] = __expf(ea);
        }
        __syncthreads();
        for (int j = 0; j < m; j++) {
            float w = sw[j];
            acc += w * xh[(size_t)ssrc[j] * 64 + t];
            den += w;
        }
        __syncthreads();
    }
    g_z2[(size_t)n * 64 + t] = acc / (den + 1e-16f) + bias[t];
}

// ---------------- decode: warp per edge, dot over 64 channels ----------------
__global__ void k_decode(int E, float* __restrict__ out) {
    const float* __restrict__ z = g_z2;
    int gid  = blockIdx.x * blockDim.x + threadIdx.x;
    int warp = gid >> 5;
    int lane = gid & 31;
    if (warp >= E) return;
    int s = g_src[warp];
    int d = g_dst[warp];
    const float* zs = z + (size_t)s * 64;
    const float* zd = z + (size_t)d * 64;
    float v = zs[lane] * zd[lane] + zs[lane + 32] * zd[lane + 32];
#pragma unroll
    for (int off = 16; off > 0; off >>= 1)
        v += __shfl_down_sync(0xFFFFFFFFu, v, off);
    if (lane == 0) out[warp] = v;
}

// ---------------- launch -----------------------------------------------------
extern "C" void kernel_launch(void* const* d_in, const int* in_sizes, int n_in,
                              void* d_out, int out_size) {
    const float* x   = (const float*)d_in[0];
    const void*  ei  = d_in[1];
    const float* W1  = (const float*)d_in[2];
    const float* as1 = (const float*)d_in[3];
    const float* ad1 = (const float*)d_in[4];
    const float* b1  = (const float*)d_in[5];
    const float* W2  = (const float*)d_in[6];
    const float* as2 = (const float*)d_in[7];
    const float* ad2 = (const float*)d_in[8];
    const float* b2  = (const float*)d_in[9];
    float*       out = (float*)d_out;

    const int N  = in_sizes[0] / 128;
    const int E  = out_size;
    const int TE = E + N;
    const int nb = (N + 255) / 256;

    // edge dtype detect + convert + hist (self-loops folded into init)
    int nwords = 2 * E < 2048 ? 2 * E : 2048;
    k_detect<<<1, 256>>>((const unsigned*)ei, nwords);
    k_init_counts<<<nb, 256>>>(N);
    k_cvt_hist<<<(E + 255) / 256, 256>>>(E, ei);

    // GEMM1 in slot 4 (ncu capture window); edge-independent so safe here
    k_mma<128, 128, 256, 0><<<dim3(2, (N + 127) / 128), 256>>>(N, x, W1, as1, ad1);

    // parallel exclusive scan -> rowptr/cursor
    k_bsum<<<nb, 256>>>(N);
    k_scan_sums<<<1, 256>>>(nb, N);
    k_scan_apply<<<nb, 256>>>(N);
    k_scatter<<<(TE + 255) / 256, 256>>>(E, N);

    // layer 1 aggregation (att logits fused into GEMM epilogue)
    k_agg1<<<N, 256>>>(b1);

    // layer 2
    k_mma<64, 256, 64, 1><<<dim3(1, (N + 127) / 128), 256>>>(N, nullptr, W2, as2, ad2);
    k_agg2<<<N, 64>>>(b2);

    // decode
    k_decode<<<(E * 32 + 255) / 256, 256>>>(E, out);
}